// round 13
// baseline (speedup 1.0000x reference)
#include <cuda_runtime.h>
#include <cuda_fp16.h>
#include <math.h>
#include <stdint.h>

// Problem constants (fixed by setup_inputs)
#define BB   4
#define LL   1024
#define EE   1024
#define HH   16
#define DD   64
#define WW   128
#define NT   (BB*LL)          // 4096 rows
#define E3   (3*EE)
#define E4   (4*EE)

#define QT   32               // queries per attention block
#define BAND (QT + 2*WW)      // 288
#define QP   72               // half pitch for Q/K/V smem (64 + 8)
#define SPH  296              // half pitch for P smem (288 + 8)

// ---------------- scratch (device globals; no allocation allowed) -------------
__device__ __half g_qkvh[NT * E3];         // fp16 qkv
__device__ __half g_ctxh[NT * EE];         // fp16 ctx (feeds out_proj A)
__device__ float  g_s1 [NT * EE];
__device__ float  g_h  [NT * EE];          // LN1 out fp32 (residual for FFN2)
__device__ __half g_hh [NT * EE];          // LN1 out fp16 (FFN1 A)
__device__ __half g_ffh[NT * E4];          // FFN1 out fp16 (FFN2 A)
__device__ float  g_s2 [NT * EE];
__device__ __half g_xh [NT * EE];          // x fp16 (QKV A)
__device__ __half g_wh [(size_t)E3*EE + (size_t)EE*EE + (size_t)E4*EE + (size_t)EE*E4];
__device__ float  g_P  [BB * HH * LL * BAND];

#define WQ_OFF 0
#define WO_OFF ((size_t)E3*EE)
#define W1_OFF (WO_OFF + (size_t)EE*EE)
#define W2_OFF (W1_OFF + (size_t)E4*EE)

// ============================ helpers =============================
__device__ __forceinline__ uint32_t smem_u32(const void* p) {
    uint32_t a;
    asm("{ .reg .u64 t; cvta.to.shared.u64 t, %1; cvt.u32.u64 %0, t; }" : "=r"(a) : "l"(p));
    return a;
}

#define CP_ASYNC16(dst, src) \
    asm volatile("cp.async.cg.shared.global [%0], [%1], 16;" :: "r"(dst), "l"(src) : "memory")
#define CP_COMMIT() asm volatile("cp.async.commit_group;" ::: "memory")

#define LDSM4(r, addr) \
    asm volatile("ldmatrix.sync.aligned.m8n8.x4.shared.b16 {%0,%1,%2,%3}, [%4];" \
        : "=r"((r)[0]), "=r"((r)[1]), "=r"((r)[2]), "=r"((r)[3]) : "r"(addr))
#define LDSM2(r, addr) \
    asm volatile("ldmatrix.sync.aligned.m8n8.x2.shared.b16 {%0,%1}, [%2];" \
        : "=r"((r)[0]), "=r"((r)[1]) : "r"(addr))
#define LDSM4T(r, addr) \
    asm volatile("ldmatrix.sync.aligned.m8n8.x4.trans.shared.b16 {%0,%1,%2,%3}, [%4];" \
        : "=r"((r)[0]), "=r"((r)[1]), "=r"((r)[2]), "=r"((r)[3]) : "r"(addr))

__device__ __forceinline__ void mma_fp16(float& d0, float& d1, float& d2, float& d3,
                                         uint32_t a0, uint32_t a1, uint32_t a2, uint32_t a3,
                                         uint32_t b0, uint32_t b1) {
    asm volatile(
        "mma.sync.aligned.m16n8k16.row.col.f32.f16.f16.f32 "
        "{%0,%1,%2,%3}, {%4,%5,%6,%7}, {%8,%9}, {%0,%1,%2,%3};"
        : "+f"(d0), "+f"(d1), "+f"(d2), "+f"(d3)
        : "r"(a0), "r"(a1), "r"(a2), "r"(a3), "r"(b0), "r"(b1));
}

// =====================================================================
// fp16 mma.sync GEMM: C[M,N] = A[M,K] * W[N,K]^T + bias (+res)(relu)
// 128x128 CTA tile, BK=64 (4 ks per barrier), 3-stage cp.async, 4 warps.
// Pipeline: wait_group -> __syncthreads -> issue load(kb+2) -> compute.
// mode bit0 = relu, bit2 = C is half array (else float).
// =====================================================================
#define P32    36                  // u32 per smem row (32 data + 4 pad; 9x16B odd -> LDSM conflict-free)
#define ATILE32 (128 * P32)        // 4608 u32 per matrix per stage
#define STAGE32 (2 * ATILE32)      // 9216 u32 = 36864 B per stage
#define GS     3
#define GSMEM_DYN (GS * STAGE32 * 4)

__global__ __launch_bounds__(128)
void gemm_mma(const __half* __restrict__ A, const __half* __restrict__ W,
              const float* __restrict__ bias, const float* __restrict__ res,
              void* __restrict__ Cv, int M, int N, int K, int mode)
{
    extern __shared__ uint32_t sh32[];
    const uint32_t shb = smem_u32(sh32);

    const int tid   = threadIdx.x;
    const int warp  = tid >> 5;
    const int lane  = tid & 31;
    const int g     = lane >> 2;
    const int t4    = lane & 3;
    const int warpM = (warp >> 1) * 64;
    const int warpN = (warp & 1) * 64;
    const int m0 = blockIdx.y * 128;
    const int n0 = blockIdx.x * 128;

    const int nk = K >> 6;                // K / 64

    const int mi = lane >> 3, lr = lane & 7;
    uint32_t abase[4], bbase[4];
#pragma unroll
    for (int mt = 0; mt < 4; mt++)
        abase[mt] = (uint32_t)((warpM + mt * 16 + (mi & 1) * 8 + lr) * P32 + (mi >> 1) * 4);
#pragma unroll
    for (int np = 0; np < 4; np++)
        bbase[np] = (uint32_t)(ATILE32 + (warpN + (2 * np + (mi >> 1)) * 8 + lr) * P32 + (mi & 1) * 4);

    float acc[4][8][4];
#pragma unroll
    for (int mt = 0; mt < 4; mt++)
#pragma unroll
        for (int nt = 0; nt < 8; nt++)
#pragma unroll
            for (int q = 0; q < 4; q++) acc[mt][nt][q] = 0.f;

    // ---- async stage loader: 2048 x 16B chunks (A 1024 + B 1024), 16/thread ----
#define LOAD_STAGE(kb, s) do {                                               \
        const uint32_t sbase = shb + (uint32_t)(s) * (STAGE32 * 4);          \
        _Pragma("unroll")                                                    \
        for (int i = 0; i < 16; i++) {                                       \
            const int idx = tid + i * 128;        /* 0..2047 */              \
            const int mat = idx >> 10;            /* 0 = A, 1 = B */         \
            const int r   = (idx >> 3) & 127;                                \
            const int c   = idx & 7;              /* 16B chunk in row */     \
            const __half* src = (mat ? (W + (size_t)(n0 + r) * K)            \
                                     : (A + (size_t)(m0 + r) * K))           \
                                + (size_t)(kb) * 64 + c * 8;                 \
            const uint32_t dst = sbase + (uint32_t)(mat * (ATILE32 * 4)      \
                               + r * (P32 * 4) + c * 16);                    \
            CP_ASYNC16(dst, src);                                            \
        }                                                                    \
        CP_COMMIT();                                                         \
    } while (0)

    LOAD_STAGE(0, 0);
    LOAD_STAGE(1, 1);

    for (int kb = 0; kb < nk; kb++) {
        // stage kb landed for this thread (newest group kb+1 may stay pending)
        const int rem = nk - 1 - kb;
        if (rem >= 1) asm volatile("cp.async.wait_group 1;" ::: "memory");
        else          asm volatile("cp.async.wait_group 0;" ::: "memory");
        // cross-thread visibility + buffer-reuse guard (all warps done with kb-1)
        __syncthreads();
        if (kb + 2 < nk) LOAD_STAGE(kb + 2, (kb + 2) % 3);

        const uint32_t stoff = shb + (uint32_t)((kb % 3) * (STAGE32 * 4));
#pragma unroll
        for (int ks = 0; ks < 4; ks++) {
            uint32_t af[4][4];
#pragma unroll
            for (int mt = 0; mt < 4; mt++)
                LDSM4(af[mt], stoff + (abase[mt] + ks * 8) * 4);
            uint32_t bf[4][4];
#pragma unroll
            for (int np = 0; np < 4; np++)
                LDSM4(bf[np], stoff + (bbase[np] + ks * 8) * 4);
#pragma unroll
            for (int mt = 0; mt < 4; mt++)
#pragma unroll
                for (int nt = 0; nt < 8; nt++) {
                    const int np = nt >> 1, j = (nt & 1) * 2;
                    mma_fp16(acc[mt][nt][0], acc[mt][nt][1], acc[mt][nt][2], acc[mt][nt][3],
                             af[mt][0], af[mt][1], af[mt][2], af[mt][3],
                             bf[np][j], bf[np][j + 1]);
                }
        }
    }
    __syncthreads();

    // ---- epilogue ----
    const bool do_relu = (mode & 1) != 0;
    const bool half_out = (mode & 4) != 0;
    float* Cf = (float*)Cv;
    __half* Ch = (__half*)Cv;
#pragma unroll
    for (int mt = 0; mt < 4; mt++) {
        const int row0 = m0 + warpM + mt * 16 + g;
        const int row1 = row0 + 8;
#pragma unroll
        for (int nt = 0; nt < 8; nt++) {
            const int col = n0 + warpN + nt * 8 + 2 * t4;
            const float2 bz = *(const float2*)&bias[col];
            float2 u, v;
            u.x = acc[mt][nt][0] + bz.x;  u.y = acc[mt][nt][1] + bz.y;
            v.x = acc[mt][nt][2] + bz.x;  v.y = acc[mt][nt][3] + bz.y;
            if (res) {
                const float2 r0 = *(const float2*)&res[(size_t)row0 * N + col];
                const float2 r1 = *(const float2*)&res[(size_t)row1 * N + col];
                u.x += r0.x; u.y += r0.y; v.x += r1.x; v.y += r1.y;
            }
            if (do_relu) {
                u.x = fmaxf(u.x, 0.f); u.y = fmaxf(u.y, 0.f);
                v.x = fmaxf(v.x, 0.f); v.y = fmaxf(v.y, 0.f);
            }
            if (half_out) {
                *(__half2*)&Ch[(size_t)row0 * N + col] = __float22half2_rn(u);
                *(__half2*)&Ch[(size_t)row1 * N + col] = __float22half2_rn(v);
            } else {
                *(float2*)&Cf[(size_t)row0 * N + col] = u;
                *(float2*)&Cf[(size_t)row1 * N + col] = v;
            }
        }
    }
#undef LOAD_STAGE
}

// =====================================================================
// fused round-to-fp16: x + all 4 weight matrices in one launch
// =====================================================================
#define XF4  (NT * EE / 4)
#define WQF4 (E3 * EE / 4)
#define WOF4 (EE * EE / 4)
#define W1F4 (E4 * EE / 4)
#define W2F4 (EE * E4 / 4)
#define TOTF4 (XF4 + WQF4 + WOF4 + W1F4 + W2F4)

__global__ __launch_bounds__(256)
void cvt_all_kernel(const float* __restrict__ x,  const float* __restrict__ wq,
                    const float* __restrict__ wo, const float* __restrict__ w1,
                    const float* __restrict__ w2)
{
    const int i = blockIdx.x * 256 + threadIdx.x;
    if (i >= TOTF4) return;
    const float4* src;
    __half* dst;
    int off = i;
    if (off < XF4)                    { src = (const float4*)x;  dst = g_xh; }
    else if ((off -= XF4) < WQF4)     { src = (const float4*)wq; dst = g_wh + WQ_OFF; }
    else if ((off -= WQF4) < WOF4)    { src = (const float4*)wo; dst = g_wh + WO_OFF; }
    else if ((off -= WOF4) < W1F4)    { src = (const float4*)w1; dst = g_wh + W1_OFF; }
    else                              { off -= W1F4; src = (const float4*)w2; dst = g_wh + W2_OFF; }
    const float4 v = src[off];
    __half2 lo = __float22half2_rn(make_float2(v.x, v.y));
    __half2 hi = __float22half2_rn(make_float2(v.z, v.w));
    uint2 pk;
    pk.x = *(uint32_t*)&lo;
    pk.y = *(uint32_t*)&hi;
    *(uint2*)&dst[(size_t)off * 4] = pk;
}

// =====================================================================
// Banded attention: fp16 tensor-core QK^T and P@V, fp32 softmax.
// One CTA (256 thr, 8 warps) per (qtile, head, batch).
// =====================================================================
#define OFF_Q 0                                 // 32 x QP halves
#define OFF_K (OFF_Q + QT * QP * 2)             // 288 x QP halves
#define OFF_V (OFF_K + BAND * QP * 2)           // 288 x QP halves
#define OFF_S (OFF_V + BAND * QP * 2)           // 32 x 288 floats
#define OFF_P (OFF_S + QT * BAND * 4)           // 32 x SPH halves
#define ATTN_SMEM (OFF_P + QT * SPH * 2)

__global__ __launch_bounds__(256, 1)
void attn_kernel(const __half* __restrict__ qkv)
{
    extern __shared__ char smc[];
    const uint32_t sb = smem_u32(smc);
    __half* sQ = (__half*)(smc + OFF_Q);
    __half* sK = (__half*)(smc + OFF_K);
    __half* sV = (__half*)(smc + OFF_V);
    float*  sS = (float*)(smc + OFF_S);
    __half* sP = (__half*)(smc + OFF_P);

    const int t  = threadIdx.x;
    const int w  = t >> 5;
    const int lane = t & 31;
    const int g  = lane >> 2;
    const int t4 = lane & 3;
    const int mi = lane >> 3;
    const int lr = lane & 7;

    const int qtile = blockIdx.x;
    const int h  = blockIdx.y;
    const int b  = blockIdx.z;
    const int q0 = qtile * QT;
    const int j0 = q0 - WW;

    {
        const int row = t >> 3, c = t & 7;
        const uint4 q = *(const uint4*)&qkv[(size_t)(b * LL + q0 + row) * E3 + h * DD + c * 8];
        *(uint4*)&sQ[row * QP + c * 8] = q;
    }
    for (int idx = t; idx < BAND * 8; idx += 256) {
        const int row = idx >> 3, c = idx & 7;
        const int j = j0 + row;
        uint4 kv = make_uint4(0, 0, 0, 0), vv = make_uint4(0, 0, 0, 0);
        if (j >= 0 && j < LL) {
            const __half* kp = &qkv[(size_t)(b * LL + j) * E3 + EE + h * DD + c * 8];
            kv = *(const uint4*)kp;
            vv = *(const uint4*)(kp + EE);
        }
        *(uint4*)&sK[row * QP + c * 8] = kv;
        *(uint4*)&sV[row * QP + c * 8] = vv;
    }
    __syncthreads();

    // ======== S = Q K^T ========
    {
        const int mh = w & 1;
        const int nb = w >> 1;
        float s[9][4];
#pragma unroll
        for (int nt = 0; nt < 9; nt++)
#pragma unroll
            for (int q = 0; q < 4; q++) s[nt][q] = 0.f;

        const uint32_t qrow = (uint32_t)(mh * 16 + (mi & 1) * 8 + lr);
        const uint32_t qcol0 = (uint32_t)((mi >> 1) * 8);
#pragma unroll
        for (int kk = 0; kk < 4; kk++) {
            uint32_t af[4];
            LDSM4(af, sb + OFF_Q + (qrow * QP + kk * 16 + qcol0) * 2);
            uint32_t bf[4][4];
#pragma unroll
            for (int p = 0; p < 4; p++) {
                const uint32_t jrow = (uint32_t)(nb * 72 + (p * 2 + (mi >> 1)) * 8 + lr);
                LDSM4(bf[p], sb + OFF_K + (jrow * QP + kk * 16 + (mi & 1) * 8) * 2);
            }
            uint32_t b8[2];
            {
                const uint32_t jrow = (uint32_t)(nb * 72 + 64 + lr);
                const uint32_t kh = (uint32_t)(((lane >> 3) & 1) * 8);
                LDSM2(b8, sb + OFF_K + (jrow * QP + kk * 16 + kh) * 2);
            }
#pragma unroll
            for (int nt = 0; nt < 8; nt++) {
                const int p = nt >> 1, j = (nt & 1) * 2;
                mma_fp16(s[nt][0], s[nt][1], s[nt][2], s[nt][3],
                         af[0], af[1], af[2], af[3], bf[p][j], bf[p][j + 1]);
            }
            mma_fp16(s[8][0], s[8][1], s[8][2], s[8][3],
                     af[0], af[1], af[2], af[3], b8[0], b8[1]);
        }
#pragma unroll
        for (int nt = 0; nt < 9; nt++) {
            const int col = nb * 72 + nt * 8 + 2 * t4;
#pragma unroll
            for (int half = 0; half < 2; half++) {
                const int qi = mh * 16 + g + half * 8;
                const float v0 = s[nt][half * 2 + 0] * 0.125f;
                const float v1 = s[nt][half * 2 + 1] * 0.125f;
                const int jA = j0 + col, jB = jA + 1;
                const bool okA = (col >= qi) && (col <= qi + 2 * WW) && (jA >= 0) && (jA < LL);
                const bool okB = (col + 1 >= qi) && (col + 1 <= qi + 2 * WW) && (jB >= 0) && (jB < LL);
                sS[qi * BAND + col]     = okA ? v0 : -1e30f;
                sS[qi * BAND + col + 1] = okB ? v1 : -1e30f;
            }
        }
    }
    __syncthreads();

    // ======== softmax (fp32, exact) + fp16 P copy ========
    {
#pragma unroll
        for (int r = 0; r < 4; r++) {
            const int row = w * 4 + r;
            float vals[9];
            float mx = -1e30f;
#pragma unroll
            for (int c = 0; c < 9; c++) {
                vals[c] = sS[row * BAND + lane + 32 * c];
                mx = fmaxf(mx, vals[c]);
            }
#pragma unroll
            for (int off = 16; off > 0; off >>= 1)
                mx = fmaxf(mx, __shfl_xor_sync(0xffffffffu, mx, off));
            float ssum = 0.f;
#pragma unroll
            for (int c = 0; c < 9; c++) { vals[c] = __expf(vals[c] - mx); ssum += vals[c]; }
#pragma unroll
            for (int off = 16; off > 0; off >>= 1)
                ssum += __shfl_xor_sync(0xffffffffu, ssum, off);
            const float inv = 1.f / ssum;
#pragma unroll
            for (int c = 0; c < 9; c++) {
                const float p = vals[c] * inv;
                sS[row * BAND + lane + 32 * c] = p;
                sP[row * SPH + lane + 32 * c] = __float2half_rn(p);
            }
        }
    }
    __syncthreads();

    // ======== ctx = P @ V ========
    {
        const int mh = w & 1;
        const int db = w >> 1;
        float o[2][4];
#pragma unroll
        for (int nt = 0; nt < 2; nt++)
#pragma unroll
            for (int q = 0; q < 4; q++) o[nt][q] = 0.f;

        const uint32_t prow = (uint32_t)(mh * 16 + (mi & 1) * 8 + lr);
        const uint32_t pcol0 = (uint32_t)((mi >> 1) * 8);
#pragma unroll 2
        for (int kb = 0; kb < BAND / 16; kb++) {
            uint32_t af[4];
            LDSM4(af, sb + OFF_P + (prow * SPH + kb * 16 + pcol0) * 2);
            uint32_t bf[4];
            {
                const uint32_t vrow = (uint32_t)(kb * 16 + (mi & 1) * 8 + lr);
                const uint32_t vcol = (uint32_t)(db * 16 + (mi >> 1) * 8);
                LDSM4T(bf, sb + OFF_V + (vrow * QP + vcol) * 2);
            }
            mma_fp16(o[0][0], o[0][1], o[0][2], o[0][3],
                     af[0], af[1], af[2], af[3], bf[0], bf[1]);
            mma_fp16(o[1][0], o[1][1], o[1][2], o[1][3],
                     af[0], af[1], af[2], af[3], bf[2], bf[3]);
        }
#pragma unroll
        for (int nt = 0; nt < 2; nt++) {
            const int col = h * DD + db * 16 + nt * 8 + 2 * t4;
            const int row0 = q0 + mh * 16 + g;
            *(__half2*)&g_ctxh[(size_t)(b * LL + row0) * EE + col] =
                __float22half2_rn(make_float2(o[nt][0], o[nt][1]));
            *(__half2*)&g_ctxh[(size_t)(b * LL + row0 + 8) * EE + col] =
                __float22half2_rn(make_float2(o[nt][2], o[nt][3]));
        }
    }

    // ---- dump band-packed P (fp32) ----
    {
        float* dst = &g_P[((size_t)(b * HH + h) * LL + q0) * BAND];
        const float4* src4 = (const float4*)sS;
        float4* dst4 = (float4*)dst;
        for (int idx = t; idx < QT * BAND / 4; idx += 256) dst4[idx] = src4[idx];
    }
}

// =====================================================================
// attn_weights[b,i,j] = mean_h P ; zeros outside band (float4 version)
// =====================================================================
__global__ __launch_bounds__(256)
void attn_mean_kernel(float* __restrict__ aw)
{
    const int row = blockIdx.x;
    const int b = row >> 10;
    const int i = row & (LL - 1);
    const int qt0 = (i >> 5) << 5;
    const int j0 = qt0 - WW;
    const int lo = (i - WW) > 0 ? (i - WW) : 0;
    const int hi = (i + WW) < (LL - 1) ? (i + WW) : (LL - 1);

    for (int j4 = threadIdx.x; j4 < LL / 4; j4 += 256) {
        const int j = j4 * 4;
        float4 o = make_float4(0.f, 0.f, 0.f, 0.f);
        if (j + 3 >= lo && j <= hi) {
            const int jj = j - j0;
#pragma unroll
            for (int h = 0; h < HH; h++) {
                const float4 p = *(const float4*)&g_P[((size_t)(b * HH + h) * LL + i) * BAND + jj];
                o.x += p.x; o.y += p.y; o.z += p.z; o.w += p.w;
            }
            const float inv = 1.0f / HH;
            o.x = (j     >= lo && j     <= hi) ? o.x * inv : 0.f;
            o.y = (j + 1 >= lo && j + 1 <= hi) ? o.y * inv : 0.f;
            o.z = (j + 2 >= lo && j + 2 <= hi) ? o.z * inv : 0.f;
            o.w = (j + 3 >= lo && j + 3 <= hi) ? o.w * inv : 0.f;
        }
        *(float4*)&aw[(size_t)row * LL + j] = o;
    }
}

// =====================================================================
// LayerNorm; optionally also writes fp16 copy.
// =====================================================================
__global__ __launch_bounds__(256)
void ln_kernel(const float* __restrict__ in, const float* __restrict__ g,
               const float* __restrict__ bta, float* __restrict__ out,
               __half* __restrict__ out_h)
{
    const int row = blockIdx.x;
    const int t = threadIdx.x;
    const float4 v = ((const float4*)(in + (size_t)row * EE))[t];
    float s  = v.x + v.y + v.z + v.w;
    float s2 = v.x * v.x + v.y * v.y + v.z * v.z + v.w * v.w;
#pragma unroll
    for (int off = 16; off > 0; off >>= 1) {
        s  += __shfl_xor_sync(0xffffffffu, s, off);
        s2 += __shfl_xor_sync(0xffffffffu, s2, off);
    }
    __shared__ float sa[8], sb[8];
    __shared__ float s_mu, s_inv;
    const int w = t >> 5, lane = t & 31;
    if (lane == 0) { sa[w] = s; sb[w] = s2; }
    __syncthreads();
    if (t == 0) {
        float S = 0.f, S2 = 0.f;
#pragma unroll
        for (int k = 0; k < 8; k++) { S += sa[k]; S2 += sb[k]; }
        const float mu = S / (float)EE;
        const float var = S2 / (float)EE - mu * mu;
        s_mu = mu;
        s_inv = rsqrtf(var + 1e-5f);
    }
    __syncthreads();
    const float mu = s_mu, inv = s_inv;
    const float4 gg = ((const float4*)g)[t];
    const float4 bb = ((const float4*)bta)[t];
    float4 o;
    o.x = (v.x - mu) * inv * gg.x + bb.x;
    o.y = (v.y - mu) * inv * gg.y + bb.y;
    o.z = (v.z - mu) * inv * gg.z + bb.z;
    o.w = (v.w - mu) * inv * gg.w + bb.w;
    ((float4*)(out + (size_t)row * EE))[t] = o;
    if (out_h) {
        __half2 lo = __float22half2_rn(make_float2(o.x, o.y));
        __half2 hi = __float22half2_rn(make_float2(o.z, o.w));
        uint2 pk;
        pk.x = *(uint32_t*)&lo;
        pk.y = *(uint32_t*)&hi;
        ((uint2*)(out_h + (size_t)row * EE))[t] = pk;
    }
}

// =====================================================================
extern "C" void kernel_launch(void* const* d_in, const int* in_sizes, int n_in,
                              void* d_out, int out_size)
{
    (void)in_sizes; (void)n_in; (void)out_size;
    const float* x          = (const float*)d_in[0];
    const float* in_proj_w  = (const float*)d_in[1];
    const float* in_proj_b  = (const float*)d_in[2];
    const float* out_proj_w = (const float*)d_in[3];
    const float* out_proj_b = (const float*)d_in[4];
    const float* ln1_g      = (const float*)d_in[5];
    const float* ln1_b      = (const float*)d_in[6];
    const float* w1         = (const float*)d_in[7];
    const float* b1         = (const float*)d_in[8];
    const float* w2         = (const float*)d_in[9];
    const float* b2         = (const float*)d_in[10];
    const float* ln2_g      = (const float*)d_in[11];
    const float* ln2_b      = (const float*)d_in[12];

    float* out = (float*)d_out;
    float* aw  = out + (size_t)BB * LL * EE;

    float  *p_s1, *p_h, *p_s2;
    __half *p_qkvh, *p_ctxh, *p_hh, *p_ffh, *p_xh, *p_wh;
    cudaGetSymbolAddress((void**)&p_qkvh, g_qkvh);
    cudaGetSymbolAddress((void**)&p_ctxh, g_ctxh);
    cudaGetSymbolAddress((void**)&p_s1,   g_s1);
    cudaGetSymbolAddress((void**)&p_h,    g_h);
    cudaGetSymbolAddress((void**)&p_hh,   g_hh);
    cudaGetSymbolAddress((void**)&p_ffh,  g_ffh);
    cudaGetSymbolAddress((void**)&p_s2,   g_s2);
    cudaGetSymbolAddress((void**)&p_xh,   g_xh);
    cudaGetSymbolAddress((void**)&p_wh,   g_wh);

    cudaFuncSetAttribute(attn_kernel, cudaFuncAttributeMaxDynamicSharedMemorySize, ATTN_SMEM);
    cudaFuncSetAttribute(gemm_mma, cudaFuncAttributeMaxDynamicSharedMemorySize, GSMEM_DYN);

    // 0. fused round-to-fp16 of x + all weights
    cvt_all_kernel<<<(TOTF4 + 255) / 256, 256>>>(x, in_proj_w, out_proj_w, w1, w2);

    // 1. QKV projection (fp16 tensor core, fp16 out)
    gemm_mma<<<dim3(E3 / 128, NT / 128), 128, GSMEM_DYN>>>(
        p_xh, p_wh + WQ_OFF, in_proj_b, nullptr, p_qkvh, NT, E3, EE, 4);
    // 2. banded attention (tensor core; writes fp16 ctx + fp32 band P)
    attn_kernel<<<dim3(LL / QT, HH, BB), 256, ATTN_SMEM>>>(p_qkvh);
    // 3. head-mean attention weights
    attn_mean_kernel<<<NT, 256>>>(aw);
    // 4. out_proj + residual(x), fp32 out
    gemm_mma<<<dim3(EE / 128, NT / 128), 128, GSMEM_DYN>>>(
        p_ctxh, p_wh + WO_OFF, out_proj_b, x, p_s1, NT, EE, EE, 0);
    // 5. LN1 -> h (fp32) + hh (fp16)
    ln_kernel<<<NT, 256>>>(p_s1, ln1_g, ln1_b, p_h, p_hh);
    // 6. FFN1 + relu, fp16 out
    gemm_mma<<<dim3(E4 / 128, NT / 128), 128, GSMEM_DYN>>>(
        p_hh, p_wh + W1_OFF, b1, nullptr, p_ffh, NT, E4, EE, 5);
    // 7. FFN2 + residual(h), fp32 out
    gemm_mma<<<dim3(EE / 128, NT / 128), 128, GSMEM_DYN>>>(
        p_ffh, p_wh + W2_OFF, b2, p_h, p_s2, NT, EE, E4, 0);
    // 8. LN2 -> out
    ln_kernel<<<NT, 256>>>(p_s2, ln2_g, ln2_b, out, nullptr);
}

// round 14
// speedup vs baseline: 1.0652x; 1.0652x over previous
#include <cuda_runtime.h>
#include <cuda_fp16.h>
#include <math.h>
#include <stdint.h>

// Problem constants (fixed by setup_inputs)
#define BB   4
#define LL   1024
#define EE   1024
#define HH   16
#define DD   64
#define WW   128
#define NT   (BB*LL)          // 4096 rows
#define E3   (3*EE)
#define E4   (4*EE)

#define QT   32               // queries per attention block
#define BAND (QT + 2*WW)      // 288
#define QP   72               // half pitch for Q/K/V smem (64 + 8)
#define SPH  296              // half pitch for P smem (288 + 8)

// ---------------- scratch (device globals; no allocation allowed) -------------
__device__ __half g_qkvh[NT * E3];         // fp16 qkv
__device__ __half g_ctxh[NT * EE];         // fp16 ctx (feeds out_proj A)
__device__ float  g_s1 [NT * EE];
__device__ float  g_h  [NT * EE];          // LN1 out fp32 (residual for FFN2)
__device__ __half g_hh [NT * EE];          // LN1 out fp16 (FFN1 A)
__device__ __half g_ffh[NT * E4];          // FFN1 out fp16 (FFN2 A)
__device__ float  g_s2 [NT * EE];
__device__ __half g_xh [NT * EE];          // x fp16 (QKV A)
__device__ __half g_wh [(size_t)E3*EE + (size_t)EE*EE + (size_t)E4*EE + (size_t)EE*E4];
__device__ __half g_Ph [BB * HH * LL * BAND];   // band-packed probs (fp16)

#define WQ_OFF 0
#define WO_OFF ((size_t)E3*EE)
#define W1_OFF (WO_OFF + (size_t)EE*EE)
#define W2_OFF (W1_OFF + (size_t)E4*EE)

// ============================ helpers =============================
__device__ __forceinline__ uint32_t smem_u32(const void* p) {
    uint32_t a;
    asm("{ .reg .u64 t; cvta.to.shared.u64 t, %1; cvt.u32.u64 %0, t; }" : "=r"(a) : "l"(p));
    return a;
}

#define CP_ASYNC16(dst, src) \
    asm volatile("cp.async.cg.shared.global [%0], [%1], 16;" :: "r"(dst), "l"(src) : "memory")
#define CP_COMMIT() asm volatile("cp.async.commit_group;" ::: "memory")

#define LDSM4(r, addr) \
    asm volatile("ldmatrix.sync.aligned.m8n8.x4.shared.b16 {%0,%1,%2,%3}, [%4];" \
        : "=r"((r)[0]), "=r"((r)[1]), "=r"((r)[2]), "=r"((r)[3]) : "r"(addr))
#define LDSM2(r, addr) \
    asm volatile("ldmatrix.sync.aligned.m8n8.x2.shared.b16 {%0,%1}, [%2];" \
        : "=r"((r)[0]), "=r"((r)[1]) : "r"(addr))
#define LDSM4T(r, addr) \
    asm volatile("ldmatrix.sync.aligned.m8n8.x4.trans.shared.b16 {%0,%1,%2,%3}, [%4];" \
        : "=r"((r)[0]), "=r"((r)[1]), "=r"((r)[2]), "=r"((r)[3]) : "r"(addr))

__device__ __forceinline__ void mma_fp16(float& d0, float& d1, float& d2, float& d3,
                                         uint32_t a0, uint32_t a1, uint32_t a2, uint32_t a3,
                                         uint32_t b0, uint32_t b1) {
    asm volatile(
        "mma.sync.aligned.m16n8k16.row.col.f32.f16.f16.f32 "
        "{%0,%1,%2,%3}, {%4,%5,%6,%7}, {%8,%9}, {%0,%1,%2,%3};"
        : "+f"(d0), "+f"(d1), "+f"(d2), "+f"(d3)
        : "r"(a0), "r"(a1), "r"(a2), "r"(a3), "r"(b0), "r"(b1));
}

// =====================================================================
// fp16 mma.sync GEMM: C[M,N] = A[M,K] * W[N,K]^T + bias (+res)(relu)
// 128x128 CTA tile, BK=32, 4-stage cp.async, 4 warps (64x64 each).
// mode bit0 = relu, bit2 = C is half array (else float).
// =====================================================================
#define P32    20                  // u32 per smem row (16 data + 4 pad)
#define ATILE32 (128 * P32)
#define STAGE32 (2 * ATILE32)
#define GS     4
#define GSMEM_DYN (GS * STAGE32 * 4)

__global__ __launch_bounds__(128)
void gemm_mma(const __half* __restrict__ A, const __half* __restrict__ W,
              const float* __restrict__ bias, const float* __restrict__ res,
              void* __restrict__ Cv, int M, int N, int K, int mode)
{
    extern __shared__ uint32_t sh32[];
    const uint32_t shb = smem_u32(sh32);

    const int tid   = threadIdx.x;
    const int warp  = tid >> 5;
    const int lane  = tid & 31;
    const int g     = lane >> 2;
    const int t4    = lane & 3;
    const int warpM = (warp >> 1) * 64;
    const int warpN = (warp & 1) * 64;
    const int m0 = blockIdx.y * 128;
    const int n0 = blockIdx.x * 128;

    const int nk = K >> 5;

    const int mi = lane >> 3, lr = lane & 7;
    uint32_t abase[4], bbase[4];
#pragma unroll
    for (int mt = 0; mt < 4; mt++)
        abase[mt] = (uint32_t)((warpM + mt * 16 + (mi & 1) * 8 + lr) * P32 + (mi >> 1) * 4);
#pragma unroll
    for (int np = 0; np < 4; np++)
        bbase[np] = (uint32_t)(ATILE32 + (warpN + (2 * np + (mi >> 1)) * 8 + lr) * P32 + (mi & 1) * 4);

    float acc[4][8][4];
#pragma unroll
    for (int mt = 0; mt < 4; mt++)
#pragma unroll
        for (int nt = 0; nt < 8; nt++)
#pragma unroll
            for (int q = 0; q < 4; q++) acc[mt][nt][q] = 0.f;

#define LOAD_STAGE(kb, s) do {                                               \
        const uint32_t sbase = shb + (uint32_t)(s) * (STAGE32 * 4);          \
        _Pragma("unroll")                                                    \
        for (int i = 0; i < 8; i++) {                                        \
            const int idx = tid + i * 128;                                   \
            const int mat = idx >> 9;                                        \
            const int r   = (idx >> 2) & 127;                                \
            const int c   = idx & 3;                                         \
            const __half* src = (mat ? (W + (size_t)(n0 + r) * K)            \
                                     : (A + (size_t)(m0 + r) * K))           \
                                + (size_t)(kb) * 32 + c * 8;                 \
            const uint32_t dst = sbase + (uint32_t)(mat * (ATILE32 * 4)      \
                               + r * (P32 * 4) + c * 16);                    \
            CP_ASYNC16(dst, src);                                            \
        }                                                                    \
        CP_COMMIT();                                                         \
    } while (0)

    LOAD_STAGE(0, 0);
    LOAD_STAGE(1, 1);

    for (int kb = 0; kb < nk; kb++) {
        if (kb + 2 < nk) LOAD_STAGE(kb + 2, (kb + 2) & 3);
        const int rem = nk - 1 - kb;
        if (rem >= 2)      asm volatile("cp.async.wait_group 2;" ::: "memory");
        else if (rem == 1) asm volatile("cp.async.wait_group 1;" ::: "memory");
        else               asm volatile("cp.async.wait_group 0;" ::: "memory");
        __syncthreads();

        const uint32_t stoff = shb + (uint32_t)((kb & 3) * (STAGE32 * 4));
#pragma unroll
        for (int ks = 0; ks < 2; ks++) {
            uint32_t af[4][4];
#pragma unroll
            for (int mt = 0; mt < 4; mt++)
                LDSM4(af[mt], stoff + (abase[mt] + ks * 8) * 4);
            uint32_t bf[4][4];
#pragma unroll
            for (int np = 0; np < 4; np++)
                LDSM4(bf[np], stoff + (bbase[np] + ks * 8) * 4);
#pragma unroll
            for (int mt = 0; mt < 4; mt++)
#pragma unroll
                for (int nt = 0; nt < 8; nt++) {
                    const int np = nt >> 1, j = (nt & 1) * 2;
                    mma_fp16(acc[mt][nt][0], acc[mt][nt][1], acc[mt][nt][2], acc[mt][nt][3],
                             af[mt][0], af[mt][1], af[mt][2], af[mt][3],
                             bf[np][j], bf[np][j + 1]);
                }
        }
    }
    __syncthreads();

    const bool do_relu = (mode & 1) != 0;
    const bool half_out = (mode & 4) != 0;
    float* Cf = (float*)Cv;
    __half* Ch = (__half*)Cv;
#pragma unroll
    for (int mt = 0; mt < 4; mt++) {
        const int row0 = m0 + warpM + mt * 16 + g;
        const int row1 = row0 + 8;
#pragma unroll
        for (int nt = 0; nt < 8; nt++) {
            const int col = n0 + warpN + nt * 8 + 2 * t4;
            const float2 bz = *(const float2*)&bias[col];
            float2 u, v;
            u.x = acc[mt][nt][0] + bz.x;  u.y = acc[mt][nt][1] + bz.y;
            v.x = acc[mt][nt][2] + bz.x;  v.y = acc[mt][nt][3] + bz.y;
            if (res) {
                const float2 r0 = *(const float2*)&res[(size_t)row0 * N + col];
                const float2 r1 = *(const float2*)&res[(size_t)row1 * N + col];
                u.x += r0.x; u.y += r0.y; v.x += r1.x; v.y += r1.y;
            }
            if (do_relu) {
                u.x = fmaxf(u.x, 0.f); u.y = fmaxf(u.y, 0.f);
                v.x = fmaxf(v.x, 0.f); v.y = fmaxf(v.y, 0.f);
            }
            if (half_out) {
                *(__half2*)&Ch[(size_t)row0 * N + col] = __float22half2_rn(u);
                *(__half2*)&Ch[(size_t)row1 * N + col] = __float22half2_rn(v);
            } else {
                *(float2*)&Cf[(size_t)row0 * N + col] = u;
                *(float2*)&Cf[(size_t)row1 * N + col] = v;
            }
        }
    }
#undef LOAD_STAGE
}

// =====================================================================
// fused round-to-fp16: x + all 4 weight matrices in one launch
// =====================================================================
#define XF4  (NT * EE / 4)
#define WQF4 (E3 * EE / 4)
#define WOF4 (EE * EE / 4)
#define W1F4 (E4 * EE / 4)
#define W2F4 (EE * E4 / 4)
#define TOTF4 (XF4 + WQF4 + WOF4 + W1F4 + W2F4)

__global__ __launch_bounds__(256)
void cvt_all_kernel(const float* __restrict__ x,  const float* __restrict__ wq,
                    const float* __restrict__ wo, const float* __restrict__ w1,
                    const float* __restrict__ w2)
{
    const int i = blockIdx.x * 256 + threadIdx.x;
    if (i >= TOTF4) return;
    const float4* src;
    __half* dst;
    int off = i;
    if (off < XF4)                    { src = (const float4*)x;  dst = g_xh; }
    else if ((off -= XF4) < WQF4)     { src = (const float4*)wq; dst = g_wh + WQ_OFF; }
    else if ((off -= WQF4) < WOF4)    { src = (const float4*)wo; dst = g_wh + WO_OFF; }
    else if ((off -= WOF4) < W1F4)    { src = (const float4*)w1; dst = g_wh + W1_OFF; }
    else                              { off -= W1F4; src = (const float4*)w2; dst = g_wh + W2_OFF; }
    const float4 v = src[off];
    __half2 lo = __float22half2_rn(make_float2(v.x, v.y));
    __half2 hi = __float22half2_rn(make_float2(v.z, v.w));
    uint2 pk;
    pk.x = *(uint32_t*)&lo;
    pk.y = *(uint32_t*)&hi;
    *(uint2*)&dst[(size_t)off * 4] = pk;
}

// =====================================================================
// Banded attention: fp16 tensor-core QK^T and P@V, fp32 softmax.
// One CTA (256 thr, 8 warps) per (qtile, head, batch). P dumped as fp16.
// =====================================================================
#define OFF_Q 0                                 // 32 x QP halves
#define OFF_K (OFF_Q + QT * QP * 2)             // 288 x QP halves
#define OFF_V (OFF_K + BAND * QP * 2)           // 288 x QP halves
#define OFF_S (OFF_V + BAND * QP * 2)           // 32 x 288 floats
#define OFF_P (OFF_S + QT * BAND * 4)           // 32 x SPH halves
#define ATTN_SMEM (OFF_P + QT * SPH * 2)

__global__ __launch_bounds__(256, 1)
void attn_kernel(const __half* __restrict__ qkv)
{
    extern __shared__ char smc[];
    const uint32_t sb = smem_u32(smc);
    __half* sQ = (__half*)(smc + OFF_Q);
    __half* sK = (__half*)(smc + OFF_K);
    __half* sV = (__half*)(smc + OFF_V);
    float*  sS = (float*)(smc + OFF_S);
    __half* sP = (__half*)(smc + OFF_P);

    const int t  = threadIdx.x;
    const int w  = t >> 5;
    const int lane = t & 31;
    const int g  = lane >> 2;
    const int t4 = lane & 3;
    const int mi = lane >> 3;
    const int lr = lane & 7;

    const int qtile = blockIdx.x;
    const int h  = blockIdx.y;
    const int b  = blockIdx.z;
    const int q0 = qtile * QT;
    const int j0 = q0 - WW;

    {
        const int row = t >> 3, c = t & 7;
        const uint4 q = *(const uint4*)&qkv[(size_t)(b * LL + q0 + row) * E3 + h * DD + c * 8];
        *(uint4*)&sQ[row * QP + c * 8] = q;
    }
    for (int idx = t; idx < BAND * 8; idx += 256) {
        const int row = idx >> 3, c = idx & 7;
        const int j = j0 + row;
        uint4 kv = make_uint4(0, 0, 0, 0), vv = make_uint4(0, 0, 0, 0);
        if (j >= 0 && j < LL) {
            const __half* kp = &qkv[(size_t)(b * LL + j) * E3 + EE + h * DD + c * 8];
            kv = *(const uint4*)kp;
            vv = *(const uint4*)(kp + EE);
        }
        *(uint4*)&sK[row * QP + c * 8] = kv;
        *(uint4*)&sV[row * QP + c * 8] = vv;
    }
    __syncthreads();

    // ======== S = Q K^T ========
    {
        const int mh = w & 1;
        const int nb = w >> 1;
        float s[9][4];
#pragma unroll
        for (int nt = 0; nt < 9; nt++)
#pragma unroll
            for (int q = 0; q < 4; q++) s[nt][q] = 0.f;

        const uint32_t qrow = (uint32_t)(mh * 16 + (mi & 1) * 8 + lr);
        const uint32_t qcol0 = (uint32_t)((mi >> 1) * 8);
#pragma unroll
        for (int kk = 0; kk < 4; kk++) {
            uint32_t af[4];
            LDSM4(af, sb + OFF_Q + (qrow * QP + kk * 16 + qcol0) * 2);
            uint32_t bf[4][4];
#pragma unroll
            for (int p = 0; p < 4; p++) {
                const uint32_t jrow = (uint32_t)(nb * 72 + (p * 2 + (mi >> 1)) * 8 + lr);
                LDSM4(bf[p], sb + OFF_K + (jrow * QP + kk * 16 + (mi & 1) * 8) * 2);
            }
            uint32_t b8[2];
            {
                const uint32_t jrow = (uint32_t)(nb * 72 + 64 + lr);
                const uint32_t kh = (uint32_t)(((lane >> 3) & 1) * 8);
                LDSM2(b8, sb + OFF_K + (jrow * QP + kk * 16 + kh) * 2);
            }
#pragma unroll
            for (int nt = 0; nt < 8; nt++) {
                const int p = nt >> 1, j = (nt & 1) * 2;
                mma_fp16(s[nt][0], s[nt][1], s[nt][2], s[nt][3],
                         af[0], af[1], af[2], af[3], bf[p][j], bf[p][j + 1]);
            }
            mma_fp16(s[8][0], s[8][1], s[8][2], s[8][3],
                     af[0], af[1], af[2], af[3], b8[0], b8[1]);
        }
#pragma unroll
        for (int nt = 0; nt < 9; nt++) {
            const int col = nb * 72 + nt * 8 + 2 * t4;
#pragma unroll
            for (int half = 0; half < 2; half++) {
                const int qi = mh * 16 + g + half * 8;
                const float v0 = s[nt][half * 2 + 0] * 0.125f;
                const float v1 = s[nt][half * 2 + 1] * 0.125f;
                const int jA = j0 + col, jB = jA + 1;
                const bool okA = (col >= qi) && (col <= qi + 2 * WW) && (jA >= 0) && (jA < LL);
                const bool okB = (col + 1 >= qi) && (col + 1 <= qi + 2 * WW) && (jB >= 0) && (jB < LL);
                sS[qi * BAND + col]     = okA ? v0 : -1e30f;
                sS[qi * BAND + col + 1] = okB ? v1 : -1e30f;
            }
        }
    }
    __syncthreads();

    // ======== softmax (fp32, exact) -> fp16 P ========
    {
#pragma unroll
        for (int r = 0; r < 4; r++) {
            const int row = w * 4 + r;
            float vals[9];
            float mx = -1e30f;
#pragma unroll
            for (int c = 0; c < 9; c++) {
                vals[c] = sS[row * BAND + lane + 32 * c];
                mx = fmaxf(mx, vals[c]);
            }
#pragma unroll
            for (int off = 16; off > 0; off >>= 1)
                mx = fmaxf(mx, __shfl_xor_sync(0xffffffffu, mx, off));
            float ssum = 0.f;
#pragma unroll
            for (int c = 0; c < 9; c++) { vals[c] = __expf(vals[c] - mx); ssum += vals[c]; }
#pragma unroll
            for (int off = 16; off > 0; off >>= 1)
                ssum += __shfl_xor_sync(0xffffffffu, ssum, off);
            const float inv = 1.f / ssum;
#pragma unroll
            for (int c = 0; c < 9; c++)
                sP[row * SPH + lane + 32 * c] = __float2half_rn(vals[c] * inv);
        }
    }
    __syncthreads();

    // ======== ctx = P @ V ========
    {
        const int mh = w & 1;
        const int db = w >> 1;
        float o[2][4];
#pragma unroll
        for (int nt = 0; nt < 2; nt++)
#pragma unroll
            for (int q = 0; q < 4; q++) o[nt][q] = 0.f;

        const uint32_t prow = (uint32_t)(mh * 16 + (mi & 1) * 8 + lr);
        const uint32_t pcol0 = (uint32_t)((mi >> 1) * 8);
#pragma unroll 2
        for (int kb = 0; kb < BAND / 16; kb++) {
            uint32_t af[4];
            LDSM4(af, sb + OFF_P + (prow * SPH + kb * 16 + pcol0) * 2);
            uint32_t bf[4];
            {
                const uint32_t vrow = (uint32_t)(kb * 16 + (mi & 1) * 8 + lr);
                const uint32_t vcol = (uint32_t)(db * 16 + (mi >> 1) * 8);
                LDSM4T(bf, sb + OFF_V + (vrow * QP + vcol) * 2);
            }
            mma_fp16(o[0][0], o[0][1], o[0][2], o[0][3],
                     af[0], af[1], af[2], af[3], bf[0], bf[1]);
            mma_fp16(o[1][0], o[1][1], o[1][2], o[1][3],
                     af[0], af[1], af[2], af[3], bf[2], bf[3]);
        }
#pragma unroll
        for (int nt = 0; nt < 2; nt++) {
            const int col = h * DD + db * 16 + nt * 8 + 2 * t4;
            const int row0 = q0 + mh * 16 + g;
            *(__half2*)&g_ctxh[(size_t)(b * LL + row0) * EE + col] =
                __float22half2_rn(make_float2(o[nt][0], o[nt][1]));
            *(__half2*)&g_ctxh[(size_t)(b * LL + row0 + 8) * EE + col] =
                __float22half2_rn(make_float2(o[nt][2], o[nt][3]));
        }
    }

    // ---- dump band-packed P (fp16) ----
    {
        __half* dst = &g_Ph[((size_t)(b * HH + h) * LL + q0) * BAND];
        for (int idx = t; idx < QT * (BAND / 8); idx += 256) {
            const int row = idx / (BAND / 8);
            const int c   = idx % (BAND / 8);
            *(uint4*)&dst[row * BAND + c * 8] = *(const uint4*)&sP[row * SPH + c * 8];
        }
    }
}

// =====================================================================
// attn_weights[b,i,j] = mean_h P (fp16 in, fp32 out); zeros outside band
// =====================================================================
__global__ __launch_bounds__(256)
void attn_mean_kernel(float* __restrict__ aw)
{
    const int row = blockIdx.x;
    const int b = row >> 10;
    const int i = row & (LL - 1);
    const int qt0 = (i >> 5) << 5;
    const int j0 = qt0 - WW;
    const int lo = (i - WW) > 0 ? (i - WW) : 0;
    const int hi = (i + WW) < (LL - 1) ? (i + WW) : (LL - 1);

    for (int j4 = threadIdx.x; j4 < LL / 4; j4 += 256) {
        const int j = j4 * 4;
        float4 o = make_float4(0.f, 0.f, 0.f, 0.f);
        if (j + 3 >= lo && j <= hi) {
            const int jj = j - j0;       // 4-aligned band offset -> 8B-aligned halves
#pragma unroll
            for (int h = 0; h < HH; h++) {
                const uint2 raw = *(const uint2*)&g_Ph[((size_t)(b * HH + h) * LL + i) * BAND + jj];
                const float2 f01 = __half22float2(*(const __half2*)&raw.x);
                const float2 f23 = __half22float2(*(const __half2*)&raw.y);
                o.x += f01.x; o.y += f01.y; o.z += f23.x; o.w += f23.y;
            }
            const float inv = 1.0f / HH;
            o.x = (j     >= lo && j     <= hi) ? o.x * inv : 0.f;
            o.y = (j + 1 >= lo && j + 1 <= hi) ? o.y * inv : 0.f;
            o.z = (j + 2 >= lo && j + 2 <= hi) ? o.z * inv : 0.f;
            o.w = (j + 3 >= lo && j + 3 <= hi) ? o.w * inv : 0.f;
        }
        *(float4*)&aw[(size_t)row * LL + j] = o;
    }
}

// =====================================================================
// LayerNorm; optionally also writes fp16 copy.
// =====================================================================
__global__ __launch_bounds__(256)
void ln_kernel(const float* __restrict__ in, const float* __restrict__ g,
               const float* __restrict__ bta, float* __restrict__ out,
               __half* __restrict__ out_h)
{
    const int row = blockIdx.x;
    const int t = threadIdx.x;
    const float4 v = ((const float4*)(in + (size_t)row * EE))[t];
    float s  = v.x + v.y + v.z + v.w;
    float s2 = v.x * v.x + v.y * v.y + v.z * v.z + v.w * v.w;
#pragma unroll
    for (int off = 16; off > 0; off >>= 1) {
        s  += __shfl_xor_sync(0xffffffffu, s, off);
        s2 += __shfl_xor_sync(0xffffffffu, s2, off);
    }
    __shared__ float sa[8], sb[8];
    __shared__ float s_mu, s_inv;
    const int w = t >> 5, lane = t & 31;
    if (lane == 0) { sa[w] = s; sb[w] = s2; }
    __syncthreads();
    if (t == 0) {
        float S = 0.f, S2 = 0.f;
#pragma unroll
        for (int k = 0; k < 8; k++) { S += sa[k]; S2 += sb[k]; }
        const float mu = S / (float)EE;
        const float var = S2 / (float)EE - mu * mu;
        s_mu = mu;
        s_inv = rsqrtf(var + 1e-5f);
    }
    __syncthreads();
    const float mu = s_mu, inv = s_inv;
    const float4 gg = ((const float4*)g)[t];
    const float4 bb = ((const float4*)bta)[t];
    float4 o;
    o.x = (v.x - mu) * inv * gg.x + bb.x;
    o.y = (v.y - mu) * inv * gg.y + bb.y;
    o.z = (v.z - mu) * inv * gg.z + bb.z;
    o.w = (v.w - mu) * inv * gg.w + bb.w;
    ((float4*)(out + (size_t)row * EE))[t] = o;
    if (out_h) {
        __half2 lo = __float22half2_rn(make_float2(o.x, o.y));
        __half2 hi = __float22half2_rn(make_float2(o.z, o.w));
        uint2 pk;
        pk.x = *(uint32_t*)&lo;
        pk.y = *(uint32_t*)&hi;
        ((uint2*)(out_h + (size_t)row * EE))[t] = pk;
    }
}

// =====================================================================
extern "C" void kernel_launch(void* const* d_in, const int* in_sizes, int n_in,
                              void* d_out, int out_size)
{
    (void)in_sizes; (void)n_in; (void)out_size;
    const float* x          = (const float*)d_in[0];
    const float* in_proj_w  = (const float*)d_in[1];
    const float* in_proj_b  = (const float*)d_in[2];
    const float* out_proj_w = (const float*)d_in[3];
    const float* out_proj_b = (const float*)d_in[4];
    const float* ln1_g      = (const float*)d_in[5];
    const float* ln1_b      = (const float*)d_in[6];
    const float* w1         = (const float*)d_in[7];
    const float* b1         = (const float*)d_in[8];
    const float* w2         = (const float*)d_in[9];
    const float* b2         = (const float*)d_in[10];
    const float* ln2_g      = (const float*)d_in[11];
    const float* ln2_b      = (const float*)d_in[12];

    float* out = (float*)d_out;
    float* aw  = out + (size_t)BB * LL * EE;

    float  *p_s1, *p_h, *p_s2;
    __half *p_qkvh, *p_ctxh, *p_hh, *p_ffh, *p_xh, *p_wh;
    cudaGetSymbolAddress((void**)&p_qkvh, g_qkvh);
    cudaGetSymbolAddress((void**)&p_ctxh, g_ctxh);
    cudaGetSymbolAddress((void**)&p_s1,   g_s1);
    cudaGetSymbolAddress((void**)&p_h,    g_h);
    cudaGetSymbolAddress((void**)&p_hh,   g_hh);
    cudaGetSymbolAddress((void**)&p_ffh,  g_ffh);
    cudaGetSymbolAddress((void**)&p_s2,   g_s2);
    cudaGetSymbolAddress((void**)&p_xh,   g_xh);
    cudaGetSymbolAddress((void**)&p_wh,   g_wh);

    cudaFuncSetAttribute(attn_kernel, cudaFuncAttributeMaxDynamicSharedMemorySize, ATTN_SMEM);
    cudaFuncSetAttribute(gemm_mma, cudaFuncAttributeMaxDynamicSharedMemorySize, GSMEM_DYN);

    // 0. fused round-to-fp16 of x + all weights
    cvt_all_kernel<<<(TOTF4 + 255) / 256, 256>>>(x, in_proj_w, out_proj_w, w1, w2);

    // 1. QKV projection (fp16 tensor core, fp16 out)
    gemm_mma<<<dim3(E3 / 128, NT / 128), 128, GSMEM_DYN>>>(
        p_xh, p_wh + WQ_OFF, in_proj_b, nullptr, p_qkvh, NT, E3, EE, 4);
    // 2. banded attention (tensor core; writes fp16 ctx + fp16 band P)
    attn_kernel<<<dim3(LL / QT, HH, BB), 256, ATTN_SMEM>>>(p_qkvh);
    // 3. head-mean attention weights
    attn_mean_kernel<<<NT, 256>>>(aw);
    // 4. out_proj + residual(x), fp32 out
    gemm_mma<<<dim3(EE / 128, NT / 128), 128, GSMEM_DYN>>>(
        p_ctxh, p_wh + WO_OFF, out_proj_b, x, p_s1, NT, EE, EE, 0);
    // 5. LN1 -> h (fp32) + hh (fp16)
    ln_kernel<<<NT, 256>>>(p_s1, ln1_g, ln1_b, p_h, p_hh);
    // 6. FFN1 + relu, fp16 out
    gemm_mma<<<dim3(E4 / 128, NT / 128), 128, GSMEM_DYN>>>(
        p_hh, p_wh + W1_OFF, b1, nullptr, p_ffh, NT, E4, EE, 5);
    // 7. FFN2 + residual(h), fp32 out
    gemm_mma<<<dim3(EE / 128, NT / 128), 128, GSMEM_DYN>>>(
        p_ffh, p_wh + W2_OFF, b2, p_h, p_s2, NT, EE, E4, 0);
    // 8. LN2 -> out
    ln_kernel<<<NT, 256>>>(p_s2, ln2_g, ln2_b, out, nullptr);
}